// round 17
// baseline (speedup 1.0000x reference)
#include <cuda_runtime.h>
#include <cuda_bf16.h>
#include <cuda_fp16.h>
#include <mma.h>
#include <math.h>

using namespace nvcuda;

// Problem shape (fixed): T=256, B=64, D=H=1024
#define TT 256
#define BB 64
#define HH 1024
#define NG 4096      // 4*H
#define TBm 16384    // T*B
#define PKCTA 128    // persistent CTAs
#define BSTR 64      // ints between spread barrier counters (256B)
#define NGRP 8       // spread counters per step (16 producer CTAs each)

// ---------------- scratch (device globals) ------------------------------------
__device__ float g_zxp[(size_t)TBm * NG];      // packed x-projection (+bias)
// h sequence, CTA-block-major: [slot(257)][cb(128)][row(64)][8] fp16
__device__ __align__(128) __half g_hseq[(size_t)(TT + 1) * BB * HH];
__device__ __align__(128) __half g_xf[(size_t)TBm * HH];     // x fp16 (row-major)
__device__ __align__(128) __half g_wxh[(size_t)HH * NG];     // input-W fp16 hi
__device__ __align__(128) __half g_wxl[(size_t)HH * NG];     // input-W fp16 lo
__device__ __align__(128) __half g_wph[(size_t)HH * NG];     // packed recurrent W hi
__device__ __align__(128) __half g_wpl[(size_t)HH * NG];     // packed recurrent W lo
// spread barrier: [layer][t][group] counters, 256B apart
__device__ __align__(128) int g_bar[2 * TT * NGRP * BSTR];   // 1 MB

// ---------------- helpers ------------------------------------------------------
__device__ __forceinline__ void split_f16(float x, __half& hi, __half& lo) {
    hi = __float2half(x);
    lo = __float2half(x - __half2float(hi));
}
__device__ __forceinline__ float fsig(float x) { return __fdividef(1.0f, 1.0f + __expf(-x)); }
__device__ __forceinline__ float ftanh(float x) { return 1.0f - __fdividef(2.0f, __expf(2.0f * x) + 1.0f); }
__device__ __forceinline__ void cpa16(void* dst, const void* src) {
    unsigned d = (unsigned)__cvta_generic_to_shared(dst);
    asm volatile("cp.async.cg.shared.global [%0], [%1], 16;" :: "r"(d), "l"(src));
}
__device__ __forceinline__ int ldrelax(const int* p) {
    int v; asm volatile("ld.relaxed.gpu.global.b32 %0, [%1];" : "=r"(v) : "l"(p)); return v;
}

__global__ void init_state_kernel(__half* hseq, int* bar) {
    int i = blockIdx.x * blockDim.x + threadIdx.x;
    int n = blockDim.x * gridDim.x;
    for (int k = i; k < BB * HH; k += n) hseq[k] = __float2half(0.0f);  // h(0)=0
    for (int k = i; k < TT * NGRP * BSTR; k += n) bar[k] = 0;
}

// fp32 -> single fp16 plane
__global__ void tof16_kernel(const float* __restrict__ a, __half* __restrict__ o, size_t n) {
    for (size_t i = (size_t)blockIdx.x * blockDim.x + threadIdx.x; i < n;
         i += (size_t)gridDim.x * blockDim.x)
        o[i] = __float2half(a[i]);
}

// Fused W prep, coalesced-write form.
// First half (o < HH*NG): x-projection planes, identity layout.
// Second half: recurrent slices, OUTPUT-linear (stores fully coalesced; the
// scattered 32B reads are absorbed by L2 since W (32MB) fits in L2 (126MB)).
template <int NEED_XLO, int NEED_RLO>
__global__ void prep_w_all(const float* __restrict__ W,
                           __half* __restrict__ xh, __half* __restrict__ xl,
                           __half* __restrict__ rh, __half* __restrict__ rl) {
    const size_t N1 = (size_t)HH * NG;
    for (size_t o = (size_t)blockIdx.x * blockDim.x + threadIdx.x;
         o < 2 * N1; o += (size_t)gridDim.x * blockDim.x) {
        if (o < N1) {
            __half h, l; split_f16(W[o], h, l);
            xh[o] = h;
            if (NEED_XLO) xl[o] = l;
        } else {
            size_t oo = o - N1;
            int j = (int)(oo & 7);
            int g = (int)((oo >> 3) & 3);
            int k = (int)((oo >> 5) & 1023);
            int c = (int)(oo >> 15);
            float v = W[(size_t)(HH + k) * NG + g * HH + c * 8 + j];
            __half h, l; split_f16(v, h, l);
            rh[oo] = h;
            if (NEED_RLO) rl[oo] = l;
        }
    }
}

// ---------------- big input-projection GEMM (fp16, fused bias+repack) ---------
#define XBM 128
#define XBN 128
#define XBK 32
#define XST 3

struct GSmem {
    union {
        struct {
            __half Af[XST][XBM][XBK + 8];
            __half Bh[XST][XBK][XBN + 8];
            __half Bl[XST][XBK][XBN + 8];
        } p;
        float stage[XBM][XBN + 8];
    };
};

template <int NPASS>
__global__ __launch_bounds__(256) void gemm_x_f16(
    const __half* __restrict__ Af, const __half* __restrict__ hseq,
    const __half* __restrict__ Bph, const __half* __restrict__ Bpl,
    const float* __restrict__ bias, float* __restrict__ zxp, int seq)
{
    extern __shared__ unsigned char sraw[];
    GSmem* S = (GSmem*)sraw;

    const int bm = blockIdx.y * XBM;
    const int bn = blockIdx.x * XBN;
    const int tid = threadIdx.x;
    const int warp = tid >> 5;
    const int wm = (warp >> 2) * 64;
    const int wn = (warp & 3) * 32;

    auto load_stage = [&](int s, int kb) {
#pragma unroll
        for (int p = 0; p < 2; ++p) {
            int i = tid + p * 256;
            int r = i >> 2, cbl = i & 3;
            if (seq == 0) {
                cpa16(&S->p.Af[s][r][cbl * 8], Af + (size_t)(bm + r) * HH + kb + cbl * 8);
            } else {
                int m = bm + r, t0 = m >> 6, row = m & 63;
                size_t src = (((size_t)(t0 + 1) * PKCTA + (kb >> 3) + cbl) * BB + row) * 8;
                cpa16(&S->p.Af[s][r][cbl * 8], hseq + src);
            }
        }
#pragma unroll
        for (int p = 0; p < 2; ++p) {
            int i = tid + p * 256;
            int r = i >> 4, off = (i & 15) * 8;
            cpa16(&S->p.Bh[s][r][off], Bph + (size_t)(kb + r) * NG + bn + off);
            if (NPASS == 2)
                cpa16(&S->p.Bl[s][r][off], Bpl + (size_t)(kb + r) * NG + bn + off);
        }
    };

    load_stage(0, 0);
    asm volatile("cp.async.commit_group;" ::: "memory");
    load_stage(1, XBK);
    asm volatile("cp.async.commit_group;" ::: "memory");

    wmma::fragment<wmma::accumulator, 16, 16, 16, float> acc[4][2];
#pragma unroll
    for (int i = 0; i < 4; ++i)
#pragma unroll
        for (int j = 0; j < 2; ++j) wmma::fill_fragment(acc[i][j], 0.0f);

    const int NKT = HH / XBK;   // 32
    for (int kt = 0; kt < NKT; ++kt) {
        asm volatile("cp.async.wait_group 1;" ::: "memory");
        __syncthreads();
        int s = kt % XST;

#pragma unroll
        for (int kk = 0; kk < XBK; kk += 16) {
            wmma::fragment<wmma::matrix_a, 16, 16, 16, __half, wmma::row_major> af[4];
            wmma::fragment<wmma::matrix_b, 16, 16, 16, __half, wmma::row_major> bh[2], bl[2];
#pragma unroll
            for (int i = 0; i < 4; ++i)
                wmma::load_matrix_sync(af[i], &S->p.Af[s][wm + 16 * i][kk], XBK + 8);
#pragma unroll
            for (int j = 0; j < 2; ++j) {
                wmma::load_matrix_sync(bh[j], &S->p.Bh[s][kk][wn + 16 * j], XBN + 8);
                if (NPASS == 2)
                    wmma::load_matrix_sync(bl[j], &S->p.Bl[s][kk][wn + 16 * j], XBN + 8);
            }
#pragma unroll
            for (int i = 0; i < 4; ++i)
#pragma unroll
                for (int j = 0; j < 2; ++j) {
                    wmma::mma_sync(acc[i][j], af[i], bh[j], acc[i][j]);
                    if (NPASS == 2)
                        wmma::mma_sync(acc[i][j], af[i], bl[j], acc[i][j]);
                }
        }

        if (kt + 2 < NKT) load_stage((kt + 2) % XST, (kt + 2) * XBK);
        asm volatile("cp.async.commit_group;" ::: "memory");
    }

    // fused epilogue: stage to smem, scatter to zxp packed layout + bias
    asm volatile("cp.async.wait_group 0;" ::: "memory");
    __syncthreads();
#pragma unroll
    for (int i = 0; i < 4; ++i)
#pragma unroll
        for (int j = 0; j < 2; ++j)
            wmma::store_matrix_sync(&S->stage[wm + 16 * i][wn + 16 * j], acc[i][j],
                                    XBN + 8, wmma::mem_row_major);
    __syncthreads();

    {
        const int j8 = tid & 7;
        const int cl = (tid >> 3) & 15;
        const int r0 = tid >> 7;
        const int g  = bn >> 10;
        const int c0 = (bn & 1023) >> 3;
        const float bval = bias[g * HH + (c0 + cl) * 8 + j8];
#pragma unroll 4
        for (int rr = r0; rr < XBM; rr += 2) {
            int m = bm + rr, t = m >> 6, row = m & 63;
            size_t o = (((size_t)t * PKCTA + c0 + cl) * BB + row) * 32 + g * 8 + j8;
            zxp[o] = S->stage[rr][cl * 8 + j8] + bval;
        }
    }
}

// ---------------- persistent recurrent kernel (fp16, NPASS template) ----------
#define CH 64
#define NCH 16
#define HSTW 40
#define WST 32
#define ZST 36

struct PSmem {
    __half wh[HH][WST];
    __half wl[HH][WST];
    __half hws[8][3][16][HSTW];
    float zxs[BB][ZST];
    float zs[2][BB][ZST];
    float cs[BB][12];
};

template <int NPASS>
__global__ __launch_bounds__(256) void lstm_persist_kernel(
    const float* __restrict__ zxp,
    const __half* __restrict__ wph,
    const __half* __restrict__ wpl,
    __half* __restrict__ hseq,
    float* __restrict__ hout_all,
    int* __restrict__ bar)           // [TT][NGRP][BSTR] spread counters
{
    extern __shared__ unsigned char smem_raw[];
    PSmem* S = (PSmem*)smem_raw;

    const int tid  = threadIdx.x;
    const int warp = tid >> 5;
    const int lane = tid & 31;
    const int cblk = blockIdx.x;
    const int mt   = warp & 3;
    const int kh   = warp >> 2;
    const int wrow = mt * 16;
    const int mygrp = cblk >> 4;     // 16 CTAs per group counter

    for (int i = tid; i < HH * 4; i += 256) {
        int row = i >> 2, off = (i & 3) * 8;
        cpa16(&S->wh[row][off], wph + ((size_t)cblk * HH + row) * 32 + off);
        if (NPASS == 2)
            cpa16(&S->wl[row][off], wpl + ((size_t)cblk * HH + row) * 32 + off);
    }
    asm volatile("cp.async.commit_group;\ncp.async.wait_group 0;" ::: "memory");
    for (int e = tid; e < BB * 12; e += 256) ((float*)S->cs)[e] = 0.0f;
    __syncthreads();

    const int frow = tid >> 2;
    const int fjp  = tid & 3;

    for (int t = 0; t < TT; ++t) {
        const __half* hin = hseq + (size_t)t * BB * HH;
        __half* hout = hseq + (size_t)(t + 1) * BB * HH + (size_t)cblk * (BB * 8);

        // zx loads issued before the wait (independent of h(t))
        {
            const float* zsrc = zxp + ((size_t)t * PKCTA + cblk) * (BB * 32);
#pragma unroll
            for (int p = 0; p < 2; ++p) {
                int i = tid + p * 256;
                int r = i >> 3, seg = i & 7;
                cpa16((char*)&S->zxs[r][0] + seg * 16, zsrc + r * 32 + seg * 4);
            }
        }

        // ---- spread-counter barrier wait: warp 0 polls all 8 group counters ----
        if (t > 0) {
            if (warp == 0) {
                const int* f = bar + (size_t)(t - 1) * NGRP * BSTR;
                for (;;) {
                    int v = (lane < NGRP) ? ldrelax(f + lane * BSTR) : 16;
                    if (__all_sync(0xffffffffu, v >= 16)) break;
                    __nanosleep(32);
                }
                asm volatile("fence.acq_rel.gpu;" ::: "memory");
            }
            __syncthreads();
        }

        auto wload = [&](int slot, int ic) {
            int cbbase = ic * 8 + kh * 4;
            int cbl = lane >> 3;
#pragma unroll
            for (int p = 0; p < 2; ++p) {
                int rlo = (lane & 7) + p * 8;
                size_t src = (((size_t)(cbbase + cbl)) * BB + wrow + rlo) * 8;
                cpa16(&S->hws[warp][slot][rlo][cbl * 8], hin + src);
            }
        };

        wload(0, 0);
        asm volatile("cp.async.commit_group;" ::: "memory");
        wload(1, 1);
        asm volatile("cp.async.commit_group;" ::: "memory");
        wload(2, 2);
        asm volatile("cp.async.commit_group;" ::: "memory");

        wmma::fragment<wmma::accumulator, 16, 16, 16, float> acc[2][2];
#pragma unroll
        for (int nt = 0; nt < 2; ++nt)
#pragma unroll
            for (int p = 0; p < NPASS; ++p) wmma::fill_fragment(acc[nt][p], 0.0f);

        for (int ic = 0; ic < NCH; ++ic) {
            asm volatile("cp.async.wait_group 2;" ::: "memory");
            int sl = ic % 3;

#pragma unroll
            for (int kk = 0; kk < 2; ++kk) {
                wmma::fragment<wmma::matrix_a, 16, 16, 16, __half, wmma::row_major> af;
                wmma::load_matrix_sync(af, &S->hws[warp][sl][0][kk * 16], HSTW);
                int krow = ic * CH + kh * 32 + kk * 16;
#pragma unroll
                for (int nt = 0; nt < 2; ++nt) {
                    wmma::fragment<wmma::matrix_b, 16, 16, 16, __half, wmma::row_major> bh, bl;
                    wmma::load_matrix_sync(bh, &S->wh[krow][nt * 16], WST);
                    if (NPASS == 2)
                        wmma::load_matrix_sync(bl, &S->wl[krow][nt * 16], WST);
                    wmma::mma_sync(acc[nt][0], af, bh, acc[nt][0]);
                    if (NPASS == 2)
                        wmma::mma_sync(acc[nt][1], af, bl, acc[nt][1]);
                }
            }

            if (ic + 3 < NCH) wload((ic + 3) % 3, ic + 3);
            asm volatile("cp.async.commit_group;" ::: "memory");
        }
        asm volatile("cp.async.wait_group 0;" ::: "memory");

#pragma unroll
        for (int nt = 0; nt < 2; ++nt) {
            if (NPASS == 2) {
#pragma unroll
                for (int e = 0; e < acc[nt][0].num_elements; ++e)
                    acc[nt][0].x[e] += acc[nt][1].x[e];
            }
            wmma::store_matrix_sync(&S->zs[kh][mt * 16][nt * 16], acc[nt][0], ZST,
                                    wmma::mem_row_major);
        }
        __syncthreads();

        {
            float nh2[2];
#pragma unroll
            for (int q = 0; q < 2; ++q) {
                int j = fjp + q * 4;
                float zi = S->zs[0][frow][j]      + S->zs[1][frow][j]      + S->zxs[frow][j];
                float zj = S->zs[0][frow][8 + j]  + S->zs[1][frow][8 + j]  + S->zxs[frow][8 + j];
                float zf = S->zs[0][frow][16 + j] + S->zs[1][frow][16 + j] + S->zxs[frow][16 + j];
                float zo = S->zs[0][frow][24 + j] + S->zs[1][frow][24 + j] + S->zxs[frow][24 + j];
                float cold = S->cs[frow][j];
                float nc = cold * fsig(zf + 1.0f) + fsig(zi) * ftanh(zj);
                float nh = ftanh(nc) * fsig(zo);
                S->cs[frow][j] = nc;
                nh2[q] = nh;
                hout[frow * 8 + j] = __float2half(nh);
            }
            __syncthreads();
            // ---- publish: release-RED to this CTA's spread group counter ----
            if (tid == 0)
                asm volatile("red.release.gpu.global.add.u32 [%0], 1;"
                             :: "l"(bar + (size_t)t * NGRP * BSTR + mygrp * BSTR)
                             : "memory");
            if (hout_all) {
                size_t ob = (size_t)t * BB * HH + (size_t)frow * HH + cblk * 8;
                hout_all[ob + fjp] = nh2[0];
                hout_all[ob + fjp + 4] = nh2[1];
            }
        }
    }
}

// ---------------- launch ------------------------------------------------------
extern "C" void kernel_launch(void* const* d_in, const int* in_sizes, int n_in,
                              void* d_out, int out_size)
{
    const float* x  = (const float*)d_in[0];
    const float* W0 = (const float*)d_in[1];
    const float* b0 = (const float*)d_in[2];
    const float* W1 = (const float*)d_in[3];
    const float* b1 = (const float*)d_in[4];
    float* out = (float*)d_out;

    float* zxp;
    __half *hseq, *xf, *wxh, *wxl, *wph, *wpl;
    int* bar;
    cudaGetSymbolAddress((void**)&zxp,  g_zxp);
    cudaGetSymbolAddress((void**)&hseq, g_hseq);
    cudaGetSymbolAddress((void**)&xf,   g_xf);
    cudaGetSymbolAddress((void**)&wxh,  g_wxh);
    cudaGetSymbolAddress((void**)&wxl,  g_wxl);
    cudaGetSymbolAddress((void**)&wph,  g_wph);
    cudaGetSymbolAddress((void**)&wpl,  g_wpl);
    cudaGetSymbolAddress((void**)&bar,  g_bar);

    const int psmem = (int)sizeof(PSmem);
    cudaFuncSetAttribute(lstm_persist_kernel<2>,
                         cudaFuncAttributeMaxDynamicSharedMemorySize, psmem);
    cudaFuncSetAttribute(lstm_persist_kernel<1>,
                         cudaFuncAttributeMaxDynamicSharedMemorySize, psmem);
    const int gsmem = (int)sizeof(GSmem);
    cudaFuncSetAttribute(gemm_x_f16<2>,
                         cudaFuncAttributeMaxDynamicSharedMemorySize, gsmem);
    cudaFuncSetAttribute(gemm_x_f16<1>,
                         cudaFuncAttributeMaxDynamicSharedMemorySize, gsmem);

    const dim3 ggrid(NG / XBN, TBm / XBM);   // (32, 128)
    const int LBAR = TT * NGRP * BSTR;

    // ---- layer 0 (2-pass everywhere: errors amplify through both layers) ----
    tof16_kernel<<<2048, 256>>>(x, xf, (size_t)TBm * HH);
    prep_w_all<1, 1><<<4096, 256>>>(W0, wxh, wxl, wph, wpl);
    init_state_kernel<<<256, 256>>>(hseq, bar);
    gemm_x_f16<2><<<ggrid, 256, gsmem>>>(xf, hseq, wxh, wxl, b0, zxp, 0);
    lstm_persist_kernel<2><<<PKCTA, 256, psmem>>>(zxp, wph, wpl, hseq, (float*)0, bar);

    // ---- layer 1 (1-pass gemm AND 1-pass recurrent) ----
    prep_w_all<0, 0><<<4096, 256>>>(W1, wxh, wxl, wph, wpl);
    gemm_x_f16<1><<<ggrid, 256, gsmem>>>(xf, hseq, wxh, wxl, b1, zxp, 1);
    init_state_kernel<<<256, 256>>>(hseq, bar + LBAR);
    lstm_persist_kernel<1><<<PKCTA, 256, psmem>>>(zxp, wph, wpl, hseq, out, bar + LBAR);
}